// round 10
// baseline (speedup 1.0000x reference)
#include <cuda_runtime.h>
#include <cuda_bf16.h>
#include <cstdint>
#include <cstddef>

#define S_DIM 8
#define U_DIM 8
#define SU    64
#define NK    12
#define NEG   17
#define ZD    64
#define CD    256
#define T_DIM 1140
#define LEN   1128
#define MROWS (SU * LEN)          // 72192 flattened (su,l) rows = 564 * 128
#define SCALE 0.125f

// Scratch: Wc[k][su*LEN + l][z]  (~222 MB)
__device__ float  g_Wc[(size_t)NK * MROWS * ZD];
__device__ double g_loss[NK];
__device__ int    g_acc[NK];

// ---------------------------------------------------------------------------
// bf16 helpers
// ---------------------------------------------------------------------------
__device__ __forceinline__ uint32_t bpack(__nv_bfloat16 x, __nv_bfloat16 y)
{
    __nv_bfloat162 t = __halves2bfloat162(x, y);
    return *reinterpret_cast<uint32_t*>(&t);
}

// mma.sync m16n8k16 bf16: d += a * b   (f32 accumulate)
__device__ __forceinline__ void mma16816(float* d, const uint32_t* a,
                                         const uint32_t* b)
{
    asm volatile(
        "mma.sync.aligned.m16n8k16.row.col.f32.bf16.bf16.f32 "
        "{%0,%1,%2,%3}, {%4,%5,%6,%7}, {%8,%9}, {%0,%1,%2,%3};"
        : "+f"(d[0]), "+f"(d[1]), "+f"(d[2]), "+f"(d[3])
        : "r"(a[0]), "r"(a[1]), "r"(a[2]), "r"(a[3]), "r"(b[0]), "r"(b[1]));
}

// split a float4 into packed bf16 hi / lo pairs
__device__ __forceinline__ void split4(const float4 v, uint2& hi, uint2& lo)
{
    __nv_bfloat16 hx = __float2bfloat16(v.x);
    __nv_bfloat16 hy = __float2bfloat16(v.y);
    __nv_bfloat16 hz = __float2bfloat16(v.z);
    __nv_bfloat16 hw = __float2bfloat16(v.w);
    hi = make_uint2(bpack(hx, hy), bpack(hz, hw));
    lo = make_uint2(bpack(__float2bfloat16(v.x - __bfloat162float(hx)),
                          __float2bfloat16(v.y - __bfloat162float(hy))),
                    bpack(__float2bfloat16(v.z - __bfloat162float(hz)),
                          __float2bfloat16(v.w - __bfloat162float(hw))));
}

// ---------------------------------------------------------------------------
// Kernel 1: ONE launch for all k, software-pipelined mainloop.
// Wc[k][r][z] = sum_d c_row(r)[d] * W[k][z][d] + b[k][z]
// 2-term bf16 split, lo*lo dropped (3 cross-products; residual ~2^-18).
// Grid (12, 564): x = k fastest (12 CTAs sharing a c row-tile are
// launch-adjacent -> c row-tile L2-hot 11 of 12 times).
// CTA = 128 rows x 64 z x K=256 (8 chunks of 32). Warp tile 32x32.
// Pipeline: prefetch chunk ch+1 to regs BEFORE the MMA phase of chunk ch,
// hiding the DRAM latency under the 24-HMMA compute phase.
// Smem stride 40 bf16: (20g + tg) mod 32 is a permutation -> conflict-free.
// ---------------------------------------------------------------------------
#define KC 32
#define SA 40
#define SB 40

__global__ __launch_bounds__(256, 2) void gemm_hmma(
    const float* __restrict__ c, const float* __restrict__ W,
    const float* __restrict__ bias)
{
    __shared__ __align__(16) __nv_bfloat16 Ahi[128 * SA];
    __shared__ __align__(16) __nv_bfloat16 Alo[128 * SA];
    __shared__ __align__(16) __nv_bfloat16 Bhi[ZD * SB];
    __shared__ __align__(16) __nv_bfloat16 Blo[ZD * SB];

    const int kk  = blockIdx.x;
    const int tid = threadIdx.x;
    const int wid = tid >> 5, lane = tid & 31;
    const int wm = (wid >> 1) * 32;       // warp M origin (0,32,64,96)
    const int wn = (wid & 1) * 32;        // warp N origin (0,32)
    const int g  = lane >> 2;             // groupID (0..7)
    const int tg = lane & 3;              // thread-in-group (0..3)
    const int r0 = blockIdx.y * 128;

    // ---- hoisted per-thread source pointers (su/l division done once) ----
    const float* aptr[4];
    int arow[4];
    #pragma unroll
    for (int i = 0; i < 4; i++) {
        int idx = tid + i * 256;          // < 1024
        int row = idx >> 3, q = idx & 7;  // 8 float4 per row
        arow[i] = row;
        int r = r0 + row;
        int su = r / LEN, l = r - su * LEN;
        aptr[i] = c + ((size_t)su * T_DIM + l) * CD + q * 4;
    }
    const float* wbase = W + (size_t)kk * ZD * CD;
    const float* bptr[2];
    int brow[2];
    #pragma unroll
    for (int i = 0; i < 2; i++) {
        int idx = tid + i * 256;          // < 512
        int row = idx >> 3, q = idx & 7;
        brow[i] = row;
        bptr[i] = wbase + (size_t)row * CD + q * 4;
    }
    const int aq4 = (tid & 7) * 4;        // smem column offset (bf16 units)

    float acc[2][4][4];
    #pragma unroll
    for (int mi = 0; mi < 2; mi++)
        #pragma unroll
        for (int ni = 0; ni < 4; ni++)
            #pragma unroll
            for (int e = 0; e < 4; e++) acc[mi][ni][e] = 0.f;

    // ---- prologue: load chunk 0 ----
    float4 pa[4], pb[2];
    #pragma unroll
    for (int i = 0; i < 4; i++) pa[i] = *(const float4*)(aptr[i]);
    #pragma unroll
    for (int i = 0; i < 2; i++) pb[i] = *(const float4*)(bptr[i]);

    for (int ch = 0; ch < CD / KC; ch++) {
        // ---- convert + store current chunk to smem ----
        #pragma unroll
        for (int i = 0; i < 4; i++) {
            uint2 hi, lo;
            split4(pa[i], hi, lo);
            *(uint2*)&Ahi[arow[i] * SA + aq4] = hi;
            *(uint2*)&Alo[arow[i] * SA + aq4] = lo;
        }
        #pragma unroll
        for (int i = 0; i < 2; i++) {
            uint2 hi, lo;
            split4(pb[i], hi, lo);
            *(uint2*)&Bhi[brow[i] * SB + aq4] = hi;
            *(uint2*)&Blo[brow[i] * SB + aq4] = lo;
        }
        __syncthreads();

        // ---- prefetch next chunk (LDG issued before MMA; latency hidden) --
        if (ch + 1 < CD / KC) {
            const int off = (ch + 1) * KC;
            #pragma unroll
            for (int i = 0; i < 4; i++)
                pa[i] = *(const float4*)(aptr[i] + off);
            #pragma unroll
            for (int i = 0; i < 2; i++)
                pb[i] = *(const float4*)(bptr[i] + off);
        }

        // ---- MMA phase: 2 k-steps of 16 ----
        #pragma unroll
        for (int ks = 0; ks < 2; ks++) {
            const int k0 = ks * 16;

            uint32_t ahi[2][4], alo[2][4];
            #pragma unroll
            for (int mi = 0; mi < 2; mi++) {
                int rA = (wm + mi * 16 + g) * SA + k0 + tg * 2;
                ahi[mi][0] = *(const uint32_t*)&Ahi[rA];
                ahi[mi][1] = *(const uint32_t*)&Ahi[rA + 8 * SA];
                ahi[mi][2] = *(const uint32_t*)&Ahi[rA + 8];
                ahi[mi][3] = *(const uint32_t*)&Ahi[rA + 8 * SA + 8];
                alo[mi][0] = *(const uint32_t*)&Alo[rA];
                alo[mi][1] = *(const uint32_t*)&Alo[rA + 8 * SA];
                alo[mi][2] = *(const uint32_t*)&Alo[rA + 8];
                alo[mi][3] = *(const uint32_t*)&Alo[rA + 8 * SA + 8];
            }
            uint32_t bhi[4][2], blo[4][2];
            #pragma unroll
            for (int ni = 0; ni < 4; ni++) {
                int rB = (wn + ni * 8 + g) * SB + k0 + tg * 2;
                bhi[ni][0] = *(const uint32_t*)&Bhi[rB];
                bhi[ni][1] = *(const uint32_t*)&Bhi[rB + 8];
                blo[ni][0] = *(const uint32_t*)&Blo[rB];
                blo[ni][1] = *(const uint32_t*)&Blo[rB + 8];
            }
            #pragma unroll
            for (int mi = 0; mi < 2; mi++)
                #pragma unroll
                for (int ni = 0; ni < 4; ni++) {
                    mma16816(acc[mi][ni], ahi[mi], bhi[ni]);
                    mma16816(acc[mi][ni], ahi[mi], blo[ni]);
                    mma16816(acc[mi][ni], alo[mi], bhi[ni]);
                    // lo x lo dropped: contributes ~2^-18 relative
                }
        }
        __syncthreads();
    }

    // ---- epilogue ----
    float* wcout = g_Wc + (size_t)kk * MROWS * ZD;
    #pragma unroll
    for (int mi = 0; mi < 2; mi++) {
        #pragma unroll
        for (int ni = 0; ni < 4; ni++) {
            int col = wn + ni * 8 + tg * 2;
            float b0 = bias[kk * ZD + col];
            float b1 = bias[kk * ZD + col + 1];
            size_t rowA = (size_t)(r0 + wm + mi * 16 + g);
            *(float2*)(wcout + rowA * ZD + col) =
                make_float2(acc[mi][ni][0] + b0, acc[mi][ni][1] + b1);
            *(float2*)(wcout + (rowA + 8) * ZD + col) =
                make_float2(acc[mi][ni][2] + b0, acc[mi][ni][3] + b1);
        }
    }
}

// ---------------------------------------------------------------------------
// Kernel 2: ONE scoring launch for all k.  Grid (12, 64, 12): z-dim = k.
// 8-lane groups own one l; lane owns 8 of 64 dims. Warp = 4 l's.
// ---------------------------------------------------------------------------
__global__ __launch_bounds__(256) void score_kernel(
    const float* __restrict__ z, const int* __restrict__ bidx,
    const int* __restrict__ sidx)
{
    const int kk = blockIdx.z;
    const int su = blockIdx.y;
    const int s = su >> 3, u = su & 7;
    const int tid = threadIdx.x;

    __shared__ int sbi[NEG];
    __shared__ float blk_loss;
    __shared__ int   blk_acc;
    if (tid < NEG) sbi[tid] = bidx[(kk * U_DIM + u) * NEG + tid];
    if (tid == 0) { blk_loss = 0.f; blk_acc = 0; }
    __syncthreads();

    const int warp = tid >> 5, lane = tid & 31;
    const int grp = lane >> 3, lg = lane & 7;
    const int gg = (blockIdx.x * 8 + warp) * 4 + grp;   // 0..383
    const int d0 = lg * 8;

    const float* wcb = g_Wc + ((size_t)kk * MROWS + (size_t)su * LEN) * ZD;
    const int*   sib = sidx + ((((size_t)kk * S_DIM + s) * U_DIM + u) * NEG) * LEN;
    const float* zsp = z + (size_t)(s * U_DIM) * T_DIM * ZD;

    float loss_local = 0.f;
    int   acc_local  = 0;

    #pragma unroll
    for (int it = 0; it < 3; it++) {
        const int l = gg + 384 * it;
        const bool valid = (l < LEN);
        const int lx = valid ? l : 0;

        const float4 wa = *(const float4*)(wcb + (size_t)lx * ZD + d0);
        const float4 wb = *(const float4*)(wcb + (size_t)lx * ZD + d0 + 4);

        float f[NEG + 1];
        {
            const float* zr = z + ((size_t)su * T_DIM + (lx + kk + 1)) * ZD + d0;
            const float4 p0 = *(const float4*)zr;
            const float4 p1 = *(const float4*)(zr + 4);
            f[0] = p0.x * wa.x + p0.y * wa.y + p0.z * wa.z + p0.w * wa.w
                 + p1.x * wb.x + p1.y * wb.y + p1.z * wb.z + p1.w * wb.w;
        }
        #pragma unroll
        for (int n = 0; n < NEG; n++) {
            const int si = sib[(size_t)n * LEN + lx];
            const int bi = sbi[n];
            const float* zr = zsp + ((size_t)bi * T_DIM + (si + kk + 1)) * ZD + d0;
            const float4 p0 = *(const float4*)zr;
            const float4 p1 = *(const float4*)(zr + 4);
            f[1 + n] = p0.x * wa.x + p0.y * wa.y + p0.z * wa.z + p0.w * wa.w
                     + p1.x * wb.x + p1.y * wb.y + p1.z * wb.z + p1.w * wb.w;
        }

        #pragma unroll
        for (int off = 4; off; off >>= 1)
            #pragma unroll
            for (int i = 0; i < NEG + 1; i++)
                f[i] += __shfl_xor_sync(0xffffffffu, f[i], off);

        f[0] *= SCALE;
        float m = f[0]; int am = 0;
        #pragma unroll
        for (int i = 1; i < NEG + 1; i++) {
            f[i] *= SCALE;
            if (f[i] > m) { m = f[i]; am = i; }
        }
        float ssum = 0.f;
        #pragma unroll
        for (int i = 0; i < NEG + 1; i++) ssum += __expf(f[i] - m);

        if (valid) {
            loss_local += (m + __logf(ssum)) - f[0];
            acc_local  += (am == 0) ? 1 : 0;
        }
    }

    float lval = (lg == 0) ? loss_local : 0.f;
    int   aval = (lg == 0) ? acc_local  : 0;
    lval += __shfl_xor_sync(0xffffffffu, lval, 8);
    lval += __shfl_xor_sync(0xffffffffu, lval, 16);
    aval += __shfl_xor_sync(0xffffffffu, aval, 8);
    aval += __shfl_xor_sync(0xffffffffu, aval, 16);
    if (lane == 0) {
        atomicAdd(&blk_loss, lval);
        atomicAdd(&blk_acc, aval);
    }
    __syncthreads();
    if (tid == 0) {
        atomicAdd(&g_loss[kk], (double)blk_loss);
        atomicAdd(&g_acc[kk], blk_acc);
    }
}

// ---------------------------------------------------------------------------
// zero / finalize.  d_out layout: [loss, acc_0 .. acc_11]
// ---------------------------------------------------------------------------
__global__ void zero_kernel()
{
    int t = threadIdx.x;
    if (t < NK) { g_loss[t] = 0.0; g_acc[t] = 0; }
}

__global__ void final_kernel(float* __restrict__ out)
{
    int t = threadIdx.x;
    if (t < NK)
        out[1 + t] = (float)((double)g_acc[t] / (double)(SU * LEN));
    if (t == 0) {
        double tot = 0.0;
        for (int i = 0; i < NK; i++) tot += g_loss[i];   // fixed order
        out[0] = (float)(tot / ((double)NK * SU * LEN));
    }
}

// ---------------------------------------------------------------------------
extern "C" void kernel_launch(void* const* d_in, const int* in_sizes, int n_in,
                              void* d_out, int out_size)
{
    const float* z    = (const float*)d_in[0];
    const float* c    = (const float*)d_in[1];
    const float* W    = (const float*)d_in[2];
    const float* b    = (const float*)d_in[3];
    const int*   bidx = (const int*)d_in[4];
    const int*   sidx = (const int*)d_in[5];
    float* out = (float*)d_out;

    zero_kernel<<<1, 32>>>();
    gemm_hmma<<<dim3(NK, 564), 256>>>(c, W, b);
    score_kernel<<<dim3(12, SU, NK), 256>>>(z, bidx, sidx);
    final_kernel<<<1, 32>>>(out);
}

// round 11
// speedup vs baseline: 1.1238x; 1.1238x over previous
#include <cuda_runtime.h>
#include <cuda_bf16.h>
#include <cstdint>
#include <cstddef>

#define S_DIM 8
#define U_DIM 8
#define SU    64
#define NK    12
#define NEG   17
#define ZD    64
#define CD    256
#define T_DIM 1140
#define LEN   1128
#define MROWS (SU * LEN)          // 72192 flattened (su,l) rows = 564 * 128
#define SCALE 0.125f

// Scratch: Wc[k][su*LEN + l][z]  (~222 MB)
__device__ float  g_Wc[(size_t)NK * MROWS * ZD];
__device__ double g_loss[NK];
__device__ int    g_acc[NK];

// ---------------------------------------------------------------------------
// bf16 helpers
// ---------------------------------------------------------------------------
__device__ __forceinline__ uint32_t bpack(__nv_bfloat16 x, __nv_bfloat16 y)
{
    __nv_bfloat162 t = __halves2bfloat162(x, y);
    return *reinterpret_cast<uint32_t*>(&t);
}

// mma.sync m16n8k16 bf16: d += a * b   (f32 accumulate)
__device__ __forceinline__ void mma16816(float* d, const uint32_t* a,
                                         const uint32_t* b)
{
    asm volatile(
        "mma.sync.aligned.m16n8k16.row.col.f32.bf16.bf16.f32 "
        "{%0,%1,%2,%3}, {%4,%5,%6,%7}, {%8,%9}, {%0,%1,%2,%3};"
        : "+f"(d[0]), "+f"(d[1]), "+f"(d[2]), "+f"(d[3])
        : "r"(a[0]), "r"(a[1]), "r"(a[2]), "r"(a[3]), "r"(b[0]), "r"(b[1]));
}

// ---------------------------------------------------------------------------
// Kernel 1 (R9 version — measured best, ~280us total inside 751us run).
// Wc[k][r][z] = sum_d c_row(r)[d] * W[k][z][d] + b[k][z]
// 2-term bf16 split, lo*lo dropped (3 cross-products; residual ~2^-18).
// Grid (12, 564): x = k fastest -> c row-tile L2-hot 11 of 12 times.
// CTA = 128 rows x 64 z x K=256 (8 chunks of 32). Warp tile 32x32.
// Default occupancy (3 CTAs/SM) provides the cross-CTA latency hiding.
// ---------------------------------------------------------------------------
#define KC 32
#define SA 40
#define SB 40

__global__ __launch_bounds__(256) void gemm_hmma(
    const float* __restrict__ c, const float* __restrict__ W,
    const float* __restrict__ bias)
{
    __shared__ __align__(16) __nv_bfloat16 Ahi[128 * SA];
    __shared__ __align__(16) __nv_bfloat16 Alo[128 * SA];
    __shared__ __align__(16) __nv_bfloat16 Bhi[ZD * SB];
    __shared__ __align__(16) __nv_bfloat16 Blo[ZD * SB];

    const int kk  = blockIdx.x;
    const int tid = threadIdx.x;
    const int wid = tid >> 5, lane = tid & 31;
    const int wm = (wid >> 1) * 32;       // warp M origin (0,32,64,96)
    const int wn = (wid & 1) * 32;        // warp N origin (0,32)
    const int g  = lane >> 2;             // groupID (0..7)
    const int tg = lane & 3;              // thread-in-group (0..3)
    const int r0 = blockIdx.y * 128;

    float acc[2][4][4];
    #pragma unroll
    for (int mi = 0; mi < 2; mi++)
        #pragma unroll
        for (int ni = 0; ni < 4; ni++)
            #pragma unroll
            for (int e = 0; e < 4; e++) acc[mi][ni][e] = 0.f;

    const float* wbase = W + (size_t)kk * ZD * CD;

    for (int ch = 0; ch < CD / KC; ch++) {
        const int k0g = ch * KC;

        // ---- load + split c tile: 128 rows x 32 d (4 float4 per thread) ----
        #pragma unroll
        for (int i = 0; i < 4; i++) {
            int idx = tid + i * 256;          // < 1024
            int row = idx >> 3, q = idx & 7;  // 8 float4 per row
            int r = r0 + row;
            int su = r / LEN, l = r - su * LEN;
            float4 v = *(const float4*)(c + ((size_t)su * T_DIM + l) * CD
                                          + k0g + q * 4);
            __nv_bfloat16 hx = __float2bfloat16(v.x);
            __nv_bfloat16 hy = __float2bfloat16(v.y);
            __nv_bfloat16 hz = __float2bfloat16(v.z);
            __nv_bfloat16 hw = __float2bfloat16(v.w);
            uint2 hi = make_uint2(bpack(hx, hy), bpack(hz, hw));
            uint2 lo = make_uint2(
                bpack(__float2bfloat16(v.x - __bfloat162float(hx)),
                      __float2bfloat16(v.y - __bfloat162float(hy))),
                bpack(__float2bfloat16(v.z - __bfloat162float(hz)),
                      __float2bfloat16(v.w - __bfloat162float(hw))));
            *(uint2*)&Ahi[row * SA + q * 4] = hi;
            *(uint2*)&Alo[row * SA + q * 4] = lo;
        }
        // ---- load + split W tile: 64 z x 32 d (2 float4 per thread) ----
        #pragma unroll
        for (int i = 0; i < 2; i++) {
            int idx = tid + i * 256;          // < 512
            int row = idx >> 3, q = idx & 7;
            float4 v = *(const float4*)(wbase + (size_t)row * CD + k0g + q * 4);
            __nv_bfloat16 hx = __float2bfloat16(v.x);
            __nv_bfloat16 hy = __float2bfloat16(v.y);
            __nv_bfloat16 hz = __float2bfloat16(v.z);
            __nv_bfloat16 hw = __float2bfloat16(v.w);
            uint2 hi = make_uint2(bpack(hx, hy), bpack(hz, hw));
            uint2 lo = make_uint2(
                bpack(__float2bfloat16(v.x - __bfloat162float(hx)),
                      __float2bfloat16(v.y - __bfloat162float(hy))),
                bpack(__float2bfloat16(v.z - __bfloat162float(hz)),
                      __float2bfloat16(v.w - __bfloat162float(hw))));
            *(uint2*)&Bhi[row * SB + q * 4] = hi;
            *(uint2*)&Blo[row * SB + q * 4] = lo;
        }
        __syncthreads();

        // ---- 2 k-steps of 16 ----
        #pragma unroll
        for (int ks = 0; ks < 2; ks++) {
            const int k0 = ks * 16;

            uint32_t ahi[2][4], alo[2][4];
            #pragma unroll
            for (int mi = 0; mi < 2; mi++) {
                int rA = (wm + mi * 16 + g) * SA + k0 + tg * 2;
                ahi[mi][0] = *(const uint32_t*)&Ahi[rA];
                ahi[mi][1] = *(const uint32_t*)&Ahi[rA + 8 * SA];
                ahi[mi][2] = *(const uint32_t*)&Ahi[rA + 8];
                ahi[mi][3] = *(const uint32_t*)&Ahi[rA + 8 * SA + 8];
                alo[mi][0] = *(const uint32_t*)&Alo[rA];
                alo[mi][1] = *(const uint32_t*)&Alo[rA + 8 * SA];
                alo[mi][2] = *(const uint32_t*)&Alo[rA + 8];
                alo[mi][3] = *(const uint32_t*)&Alo[rA + 8 * SA + 8];
            }
            uint32_t bhi[4][2], blo[4][2];
            #pragma unroll
            for (int ni = 0; ni < 4; ni++) {
                int rB = (wn + ni * 8 + g) * SB + k0 + tg * 2;
                bhi[ni][0] = *(const uint32_t*)&Bhi[rB];
                bhi[ni][1] = *(const uint32_t*)&Bhi[rB + 8];
                blo[ni][0] = *(const uint32_t*)&Blo[rB];
                blo[ni][1] = *(const uint32_t*)&Blo[rB + 8];
            }
            #pragma unroll
            for (int mi = 0; mi < 2; mi++)
                #pragma unroll
                for (int ni = 0; ni < 4; ni++) {
                    mma16816(acc[mi][ni], ahi[mi], bhi[ni]);
                    mma16816(acc[mi][ni], ahi[mi], blo[ni]);
                    mma16816(acc[mi][ni], alo[mi], bhi[ni]);
                    // lo x lo dropped: contributes ~2^-18 relative
                }
        }
        __syncthreads();
    }

    // ---- epilogue ----
    float* wcout = g_Wc + (size_t)kk * MROWS * ZD;
    #pragma unroll
    for (int mi = 0; mi < 2; mi++) {
        #pragma unroll
        for (int ni = 0; ni < 4; ni++) {
            int col = wn + ni * 8 + tg * 2;
            float b0 = bias[kk * ZD + col];
            float b1 = bias[kk * ZD + col + 1];
            size_t rowA = (size_t)(r0 + wm + mi * 16 + g);
            *(float2*)(wcout + rowA * ZD + col) =
                make_float2(acc[mi][ni][0] + b0, acc[mi][ni][1] + b1);
            *(float2*)(wcout + (rowA + 8) * ZD + col) =
                make_float2(acc[mi][ni][2] + b0, acc[mi][ni][3] + b1);
        }
    }
}

// ---------------------------------------------------------------------------
// Kernel 2: ONE scoring launch for all k.  Grid (12, 64, 12): z-dim = k.
// 8-lane groups own one l; lane owns 8 of 64 dims. Warp = 4 l's.
// NEW: block-level smem staging of seq_index. For a fixed it, the block's
// 32 groups cover 32 CONSECUTIVE l's, so the block's full si working set is
// 3*17*32 ints (6.5 KB), loaded coalesced up-front. This removes the
// DRAM-latency si -> z-gather dependency from the per-l critical path.
// ---------------------------------------------------------------------------
__global__ __launch_bounds__(256) void score_kernel(
    const float* __restrict__ z, const int* __restrict__ bidx,
    const int* __restrict__ sidx)
{
    const int kk = blockIdx.z;
    const int su = blockIdx.y;
    const int s = su >> 3, u = su & 7;
    const int tid = threadIdx.x;

    __shared__ int   sbi[NEG];
    __shared__ int   ssi[3][NEG][32];     // [it][n][l_local]
    __shared__ float blk_loss;
    __shared__ int   blk_acc;

    const int*   sib = sidx + ((((size_t)kk * S_DIM + s) * U_DIM + u) * NEG) * LEN;
    const int lbase = blockIdx.x * 32;    // block's l origin (it=0)

    if (tid < NEG) sbi[tid] = bidx[(kk * U_DIM + u) * NEG + tid];
    if (tid == 0) { blk_loss = 0.f; blk_acc = 0; }
    // stage si: 3*17*32 = 1632 ints, coalesced 128B per (it,n) row
    for (int idx = tid; idx < 3 * NEG * 32; idx += 256) {
        int it  = idx >> 9;               // idx / 512... careful: NEG*32=544
        it = idx / (NEG * 32);
        int rem = idx - it * (NEG * 32);
        int n   = rem >> 5, ll = rem & 31;
        int l   = lbase + ll + 384 * it;
        ssi[it][n][ll] = (l < LEN) ? sib[(size_t)n * LEN + l] : 0;
    }
    __syncthreads();

    const int warp = tid >> 5, lane = tid & 31;
    const int grp = lane >> 3, lg = lane & 7;
    const int lloc = warp * 4 + grp;      // 0..31 within block
    const int gg = lbase + lloc;
    const int d0 = lg * 8;

    const float* wcb = g_Wc + ((size_t)kk * MROWS + (size_t)su * LEN) * ZD;
    const float* zsp = z + (size_t)(s * U_DIM) * T_DIM * ZD;

    float loss_local = 0.f;
    int   acc_local  = 0;

    #pragma unroll
    for (int it = 0; it < 3; it++) {
        const int l = gg + 384 * it;
        const bool valid = (l < LEN);
        const int lx = valid ? l : 0;

        const float4 wa = *(const float4*)(wcb + (size_t)lx * ZD + d0);
        const float4 wb = *(const float4*)(wcb + (size_t)lx * ZD + d0 + 4);

        float f[NEG + 1];
        {
            const float* zr = z + ((size_t)su * T_DIM + (lx + kk + 1)) * ZD + d0;
            const float4 p0 = *(const float4*)zr;
            const float4 p1 = *(const float4*)(zr + 4);
            f[0] = p0.x * wa.x + p0.y * wa.y + p0.z * wa.z + p0.w * wa.w
                 + p1.x * wb.x + p1.y * wb.y + p1.z * wb.z + p1.w * wb.w;
        }
        #pragma unroll
        for (int n = 0; n < NEG; n++) {
            const int si = ssi[it][n][lloc];
            const int bi = sbi[n];
            const float* zr = zsp + ((size_t)bi * T_DIM + (si + kk + 1)) * ZD + d0;
            const float4 p0 = *(const float4*)zr;
            const float4 p1 = *(const float4*)(zr + 4);
            f[1 + n] = p0.x * wa.x + p0.y * wa.y + p0.z * wa.z + p0.w * wa.w
                     + p1.x * wb.x + p1.y * wb.y + p1.z * wb.z + p1.w * wb.w;
        }

        #pragma unroll
        for (int off = 4; off; off >>= 1)
            #pragma unroll
            for (int i = 0; i < NEG + 1; i++)
                f[i] += __shfl_xor_sync(0xffffffffu, f[i], off);

        f[0] *= SCALE;
        float m = f[0]; int am = 0;
        #pragma unroll
        for (int i = 1; i < NEG + 1; i++) {
            f[i] *= SCALE;
            if (f[i] > m) { m = f[i]; am = i; }
        }
        float ssum = 0.f;
        #pragma unroll
        for (int i = 0; i < NEG + 1; i++) ssum += __expf(f[i] - m);

        if (valid) {
            loss_local += (m + __logf(ssum)) - f[0];
            acc_local  += (am == 0) ? 1 : 0;
        }
    }

    float lval = (lg == 0) ? loss_local : 0.f;
    int   aval = (lg == 0) ? acc_local  : 0;
    lval += __shfl_xor_sync(0xffffffffu, lval, 8);
    lval += __shfl_xor_sync(0xffffffffu, lval, 16);
    aval += __shfl_xor_sync(0xffffffffu, aval, 8);
    aval += __shfl_xor_sync(0xffffffffu, aval, 16);
    if (lane == 0) {
        atomicAdd(&blk_loss, lval);
        atomicAdd(&blk_acc, aval);
    }
    __syncthreads();
    if (tid == 0) {
        atomicAdd(&g_loss[kk], (double)blk_loss);
        atomicAdd(&g_acc[kk], blk_acc);
    }
}

// ---------------------------------------------------------------------------
// zero / finalize.  d_out layout: [loss, acc_0 .. acc_11]
// ---------------------------------------------------------------------------
__global__ void zero_kernel()
{
    int t = threadIdx.x;
    if (t < NK) { g_loss[t] = 0.0; g_acc[t] = 0; }
}

__global__ void final_kernel(float* __restrict__ out)
{
    int t = threadIdx.x;
    if (t < NK)
        out[1 + t] = (float)((double)g_acc[t] / (double)(SU * LEN));
    if (t == 0) {
        double tot = 0.0;
        for (int i = 0; i < NK; i++) tot += g_loss[i];   // fixed order
        out[0] = (float)(tot / ((double)NK * SU * LEN));
    }
}

// ---------------------------------------------------------------------------
extern "C" void kernel_launch(void* const* d_in, const int* in_sizes, int n_in,
                              void* d_out, int out_size)
{
    const float* z    = (const float*)d_in[0];
    const float* c    = (const float*)d_in[1];
    const float* W    = (const float*)d_in[2];
    const float* b    = (const float*)d_in[3];
    const int*   bidx = (const int*)d_in[4];
    const int*   sidx = (const int*)d_in[5];
    float* out = (float*)d_out;

    zero_kernel<<<1, 32>>>();
    gemm_hmma<<<dim3(NK, 564), 256>>>(c, W, b);
    score_kernel<<<dim3(12, SU, NK), 256>>>(z, bidx, sidx);
    final_kernel<<<1, 32>>>(out);
}